// round 10
// baseline (speedup 1.0000x reference)
#include <cuda_runtime.h>
#include <cstdint>

// Gated delta-rule recurrent attention, single step. B=128, H=16, Dk=Dv=128.
//
// Round-9: trade the register-resident state patch for L1 residency.
// r7 (43.5us, DRAM 73%) was pinned at 8 CTAs/SM by regs=64 (s[8] = 32 regs).
// Here pass 1 loads the 16KB slice with L1-caching loads and pass 2
// RE-READS it from L1 (hit ~32cyc) instead of keeping it in registers.
// Regs ~40 -> __launch_bounds__(128,12): 12 CTAs/SM (48 warps), 12x16KB
// = 192KB of slices resident in the 228KB L1. DRAM traffic unchanged;
// 50% more phase-offset CTAs feed the memory controller.

#define BH   2048
#define DK   128
#define DV   128

__global__ __launch_bounds__(128, 12)
void delta_cell_kernel(const float* __restrict__ q,
                       const float* __restrict__ k,
                       const float* __restrict__ v,
                       const float* __restrict__ g,
                       const float* __restrict__ beta,
                       const float* __restrict__ state_in,
                       float* __restrict__ out,
                       float* __restrict__ state_out)
{
    const int bid  = blockIdx.x;         // 0..8191
    const int bh   = bid >> 2;           // (b*H + h)
    const int cb   = bid & 3;            // column block: cols [cb*32, cb*32+32)
    const int tid  = threadIdx.x;
    const int c4   = tid & 7;            // float4 col within slice (0..7)
    const int rg   = tid >> 3;           // row group (0..15), rows 8rg..8rg+7
    const int warp = tid >> 5;           // 0..3

    __shared__ float  ks[DK];
    __shared__ float  qs[DK];
    __shared__ float4 red_kv [4][8];     // one partial per warp per c4
    __shared__ float4 red_out[4][8];

    ks[tid] = k[bh * DK + tid];
    qs[tid] = q[bh * DK + tid];
    __syncthreads();

    const float decay = expf(g[bh]);
    const float bet   = beta[bh];
    const float4 vt   = ((const float4*)(v + (size_t)bh * DV))[cb * 8 + c4];

    const float4* __restrict__ st4 =
        (const float4*)(state_in  + (size_t)bh * DK * DV);
    float4* __restrict__ sto4 =
        (float4*)(state_out + (size_t)bh * DK * DV);
    const int colbase = cb * 8 + c4;     // float4 column in the 32-wide row

    // ---- Pass 1: load the thread's 8x4 patch (L1-caching), partial k-dot.
    //      Values are NOT kept in registers; pass 2 re-reads them from L1. ----
    float4 kv = make_float4(0.f, 0.f, 0.f, 0.f);
#pragma unroll
    for (int j = 0; j < 8; ++j) {
        const int row = rg * 8 + j;
        const float4 x = st4[row * 32 + colbase];   // default: cache in L1
        const float kk = ks[row];
        kv.x = fmaf(x.x, kk, kv.x);
        kv.y = fmaf(x.y, kk, kv.y);
        kv.z = fmaf(x.z, kk, kv.z);
        kv.w = fmaf(x.w, kk, kv.w);
    }
    // Combine the 4 row-groups within the warp (lane xor 8/16 keeps c4).
#pragma unroll
    for (int m = 8; m <= 16; m <<= 1) {
        kv.x += __shfl_xor_sync(0xffffffffu, kv.x, m);
        kv.y += __shfl_xor_sync(0xffffffffu, kv.y, m);
        kv.z += __shfl_xor_sync(0xffffffffu, kv.z, m);
        kv.w += __shfl_xor_sync(0xffffffffu, kv.w, m);
    }
    if ((tid & 31) < 8)
        red_kv[warp][c4] = kv;
    __syncthreads();

    // Reduce the 4 warp partials (redundantly in every thread)
    float4 kvt = make_float4(0.f, 0.f, 0.f, 0.f);
#pragma unroll
    for (int w = 0; w < 4; ++w) {
        const float4 p = red_kv[w][c4];
        kvt.x += p.x; kvt.y += p.y; kvt.z += p.z; kvt.w += p.w;
    }
    // kv_mem = decay * (state . k); delta = (v - kv_mem) * beta
    float4 delta;
    delta.x = (vt.x - decay * kvt.x) * bet;
    delta.y = (vt.y - decay * kvt.y) * bet;
    delta.z = (vt.z - decay * kvt.z) * bet;
    delta.w = (vt.w - decay * kvt.w) * bet;

    // ---- Pass 2: re-read patch (L1 hit), sn = decay*x + k*delta,
    //      evict-first store, partial q-dot ----
    float4 acc = make_float4(0.f, 0.f, 0.f, 0.f);
#pragma unroll
    for (int j = 0; j < 8; ++j) {
        const int row = rg * 8 + j;
        const float4 x  = __ldcs(&st4[row * 32 + colbase]);  // L1 hit; done with it
        const float  kk = ks[row];
        float4 sn;
        sn.x = fmaf(decay, x.x, kk * delta.x);
        sn.y = fmaf(decay, x.y, kk * delta.y);
        sn.z = fmaf(decay, x.z, kk * delta.z);
        sn.w = fmaf(decay, x.w, kk * delta.w);
        __stcs(&sto4[row * 32 + colbase], sn);
        const float qq = qs[row];
        acc.x = fmaf(sn.x, qq, acc.x);
        acc.y = fmaf(sn.y, qq, acc.y);
        acc.z = fmaf(sn.z, qq, acc.z);
        acc.w = fmaf(sn.w, qq, acc.w);
    }
#pragma unroll
    for (int m = 8; m <= 16; m <<= 1) {
        acc.x += __shfl_xor_sync(0xffffffffu, acc.x, m);
        acc.y += __shfl_xor_sync(0xffffffffu, acc.y, m);
        acc.z += __shfl_xor_sync(0xffffffffu, acc.z, m);
        acc.w += __shfl_xor_sync(0xffffffffu, acc.w, m);
    }
    if ((tid & 31) < 8)
        red_out[warp][c4] = acc;
    __syncthreads();

    // tids 0..7 finish the q-dot and write this slice's output columns
    if (tid < 8) {
        float4 o = make_float4(0.f, 0.f, 0.f, 0.f);
#pragma unroll
        for (int w = 0; w < 4; ++w) {
            const float4 p = red_out[w][c4];
            o.x += p.x; o.y += p.y; o.z += p.z; o.w += p.w;
        }
        ((float4*)(out + (size_t)bh * DV))[cb * 8 + c4] = o;
    }
}

extern "C" void kernel_launch(void* const* d_in, const int* in_sizes, int n_in,
                              void* d_out, int out_size)
{
    const float* q     = (const float*)d_in[0];  // (B,H,1,Dk)
    const float* k     = (const float*)d_in[1];  // (B,H,1,Dk)
    const float* v     = (const float*)d_in[2];  // (B,H,1,Dv)
    const float* g     = (const float*)d_in[3];  // (B,H,1)
    const float* beta  = (const float*)d_in[4];  // (B,H,1)
    const float* state = (const float*)d_in[5];  // (B,H,Dk,Dv)

    float* out       = (float*)d_out;            // first B*H*Dv floats
    float* state_out = out + (size_t)BH * DV;    // then B*H*Dk*Dv floats

    delta_cell_kernel<<<BH * 4, 128>>>(q, k, v, g, beta, state,
                                       out, state_out);
}

// round 11
// speedup vs baseline: 1.1341x; 1.1341x over previous
#include <cuda_runtime.h>
#include <cstdint>

// Gated delta-rule recurrent attention, single step. B=128, H=16, Dk=Dv=128.
//
// Round-10: deepen per-thread load batching (the one lever that has moved
// DRAM% across r1/r5/r6/r7/r9): 64 threads/CTA, each owning a 16-row x 4-col
// patch (16x LDG.128 front-batched, state register-resident). 8192 CTAs,
// 10 CTAs/SM (launch_bounds caps regs at 102). vs r7: MLP 8->16 per thread,
// independent CTAs/SM 8->10.
//
// Thread (rg, c4): c4 = tid&7 (float4 col in the 32-col slice),
// rg = tid>>3 (8 groups of 16 rows).

#define BH   2048
#define DK   128
#define DV   128

__global__ __launch_bounds__(64, 10)
void delta_cell_kernel(const float* __restrict__ q,
                       const float* __restrict__ k,
                       const float* __restrict__ v,
                       const float* __restrict__ g,
                       const float* __restrict__ beta,
                       const float* __restrict__ state_in,
                       float* __restrict__ out,
                       float* __restrict__ state_out)
{
    const int bid  = blockIdx.x;         // 0..8191
    const int bh   = bid >> 2;           // (b*H + h)
    const int cb   = bid & 3;            // column block: cols [cb*32, cb*32+32)
    const int tid  = threadIdx.x;        // 0..63
    const int c4   = tid & 7;            // float4 col within slice (0..7)
    const int rg   = tid >> 3;           // row group (0..7), rows 16rg..16rg+15
    const int warp = tid >> 5;           // 0..1

    __shared__ float  ks[DK];
    __shared__ float  qs[DK];
    __shared__ float4 red_kv [2][8];     // one partial per warp per c4
    __shared__ float4 red_out[2][8];

    ks[tid]      = k[bh * DK + tid];
    ks[tid + 64] = k[bh * DK + tid + 64];
    qs[tid]      = q[bh * DK + tid];
    qs[tid + 64] = q[bh * DK + tid + 64];
    __syncthreads();

    const float decay = expf(g[bh]);
    const float bet   = beta[bh];
    const float4 vt   = ((const float4*)(v + (size_t)bh * DV))[cb * 8 + c4];

    const float4* __restrict__ st4 =
        (const float4*)(state_in  + (size_t)bh * DK * DV);
    float4* __restrict__ sto4 =
        (float4*)(state_out + (size_t)bh * DK * DV);
    const int colbase = cb * 8 + c4;     // float4 column in the 32-wide row

    // ---- Pass 1: load the thread's 16x4 patch (16 front-batched LDG.128),
    //      keep in registers, partial k-dot ----
    float4 s[16];
    float4 kv = make_float4(0.f, 0.f, 0.f, 0.f);
#pragma unroll
    for (int j = 0; j < 16; ++j) {
        const int row = rg * 16 + j;
        const float4 x = __ldcs(&st4[row * 32 + colbase]);
        s[j] = x;
        const float kk = ks[row];
        kv.x = fmaf(x.x, kk, kv.x);
        kv.y = fmaf(x.y, kk, kv.y);
        kv.z = fmaf(x.z, kk, kv.z);
        kv.w = fmaf(x.w, kk, kv.w);
    }
    // Combine the 4 row-groups within each warp (lane bits 3,4 = rg low bits)
#pragma unroll
    for (int m = 8; m <= 16; m <<= 1) {
        kv.x += __shfl_xor_sync(0xffffffffu, kv.x, m);
        kv.y += __shfl_xor_sync(0xffffffffu, kv.y, m);
        kv.z += __shfl_xor_sync(0xffffffffu, kv.z, m);
        kv.w += __shfl_xor_sync(0xffffffffu, kv.w, m);
    }
    if ((tid & 31) < 8)
        red_kv[warp][c4] = kv;
    __syncthreads();

    // Reduce the 2 warp partials (redundantly in every thread)
    float4 kvt;
    {
        const float4 p0 = red_kv[0][c4];
        const float4 p1 = red_kv[1][c4];
        kvt.x = p0.x + p1.x; kvt.y = p0.y + p1.y;
        kvt.z = p0.z + p1.z; kvt.w = p0.w + p1.w;
    }
    // kv_mem = decay * (state . k); delta = (v - kv_mem) * beta
    float4 delta;
    delta.x = (vt.x - decay * kvt.x) * bet;
    delta.y = (vt.y - decay * kvt.y) * bet;
    delta.z = (vt.z - decay * kvt.z) * bet;
    delta.w = (vt.w - decay * kvt.w) * bet;

    // ---- Pass 2: sn = decay*s + k*delta, evict-first store, partial q-dot ----
    float4 acc = make_float4(0.f, 0.f, 0.f, 0.f);
#pragma unroll
    for (int j = 0; j < 16; ++j) {
        const int row = rg * 16 + j;
        const float kk = ks[row];
        float4 sn;
        sn.x = fmaf(decay, s[j].x, kk * delta.x);
        sn.y = fmaf(decay, s[j].y, kk * delta.y);
        sn.z = fmaf(decay, s[j].z, kk * delta.z);
        sn.w = fmaf(decay, s[j].w, kk * delta.w);
        __stcs(&sto4[row * 32 + colbase], sn);
        const float qq = qs[row];
        acc.x = fmaf(sn.x, qq, acc.x);
        acc.y = fmaf(sn.y, qq, acc.y);
        acc.z = fmaf(sn.z, qq, acc.z);
        acc.w = fmaf(sn.w, qq, acc.w);
    }
#pragma unroll
    for (int m = 8; m <= 16; m <<= 1) {
        acc.x += __shfl_xor_sync(0xffffffffu, acc.x, m);
        acc.y += __shfl_xor_sync(0xffffffffu, acc.y, m);
        acc.z += __shfl_xor_sync(0xffffffffu, acc.z, m);
        acc.w += __shfl_xor_sync(0xffffffffu, acc.w, m);
    }
    if ((tid & 31) < 8)
        red_out[warp][c4] = acc;
    __syncthreads();

    // tids 0..7 finish the q-dot and write this slice's output columns
    if (tid < 8) {
        const float4 p0 = red_out[0][c4];
        const float4 p1 = red_out[1][c4];
        float4 o;
        o.x = p0.x + p1.x; o.y = p0.y + p1.y;
        o.z = p0.z + p1.z; o.w = p0.w + p1.w;
        ((float4*)(out + (size_t)bh * DV))[cb * 8 + c4] = o;
    }
}

extern "C" void kernel_launch(void* const* d_in, const int* in_sizes, int n_in,
                              void* d_out, int out_size)
{
    const float* q     = (const float*)d_in[0];  // (B,H,1,Dk)
    const float* k     = (const float*)d_in[1];  // (B,H,1,Dk)
    const float* v     = (const float*)d_in[2];  // (B,H,1,Dv)
    const float* g     = (const float*)d_in[3];  // (B,H,1)
    const float* beta  = (const float*)d_in[4];  // (B,H,1)
    const float* state = (const float*)d_in[5];  // (B,H,Dk,Dv)

    float* out       = (float*)d_out;            // first B*H*Dv floats
    float* state_out = out + (size_t)BH * DV;    // then B*H*Dk*Dv floats

    delta_cell_kernel<<<BH * 4, 64>>>(q, k, v, g, beta, state,
                                      out, state_out);
}

// round 13
// speedup vs baseline: 1.1382x; 1.0036x over previous
#include <cuda_runtime.h>
#include <cstdint>

// Gated delta-rule recurrent attention, single step. B=128, H=16, Dk=Dv=128.
//
// Round-12 = round-11 resubmitted unchanged (round-11 bench died to a
// container infra failure, not the kernel).
//
// r11 theory: r7 (best: 43.5us, DRAM 73%) has a prologue bubble — every CTA
// does k/q LDG -> STS -> barrier before the state loads can issue. Here the
// 8 state LDG.128 (the only traffic that matters) are issued FIRST, so the
// DRAM stream starts at cycle ~0 of every CTA; the k/q round-trip and
// barrier hide under the state-load latency. k-dot moves after the barrier,
// consuming the register-resident patch.
//
// Shape (proven): 8192 CTAs x 128 threads, 32-col slices, s[8] float4 regs,
// warp-shuffle pre-reduction, __ldcs/__stcs, 8 CTAs/SM.

#define BH   2048
#define DK   128
#define DV   128

__global__ __launch_bounds__(128, 8)
void delta_cell_kernel(const float* __restrict__ q,
                       const float* __restrict__ k,
                       const float* __restrict__ v,
                       const float* __restrict__ g,
                       const float* __restrict__ beta,
                       const float* __restrict__ state_in,
                       float* __restrict__ out,
                       float* __restrict__ state_out)
{
    const int bid  = blockIdx.x;         // 0..8191
    const int bh   = bid >> 2;           // (b*H + h)
    const int cb   = bid & 3;            // column block: cols [cb*32, cb*32+32)
    const int tid  = threadIdx.x;
    const int c4   = tid & 7;            // float4 col within slice (0..7)
    const int rg   = tid >> 3;           // row group (0..15), rows 8rg..8rg+7
    const int warp = tid >> 5;           // 0..3

    __shared__ float  ks[DK];
    __shared__ float  qs[DK];
    __shared__ float4 red_kv [4][8];     // one partial per warp per c4
    __shared__ float4 red_out[4][8];

    const float4* __restrict__ st4 =
        (const float4*)(state_in  + (size_t)bh * DK * DV);
    float4* __restrict__ sto4 =
        (float4*)(state_out + (size_t)bh * DK * DV);
    const int colbase = cb * 8 + c4;     // float4 column in the 32-wide row

    // ---- Front-batched state loads: no dependency on k/q, issue first ----
    float4 s[8];
#pragma unroll
    for (int j = 0; j < 8; ++j) {
        const int row = rg * 8 + j;
        s[j] = __ldcs(&st4[row * 32 + colbase]);
    }

    // Small-tensor loads + k/q staging ride under the state-load latency.
    const float4 vt   = ((const float4*)(v + (size_t)bh * DV))[cb * 8 + c4];
    const float decay = expf(g[bh]);
    const float bet   = beta[bh];
    ks[tid] = k[bh * DK + tid];
    qs[tid] = q[bh * DK + tid];
    __syncthreads();

    // ---- Pass 1: k-dot over the register-resident 8x4 patch ----
    float4 kv = make_float4(0.f, 0.f, 0.f, 0.f);
#pragma unroll
    for (int j = 0; j < 8; ++j) {
        const float kk = ks[rg * 8 + j];
        kv.x = fmaf(s[j].x, kk, kv.x);
        kv.y = fmaf(s[j].y, kk, kv.y);
        kv.z = fmaf(s[j].z, kk, kv.z);
        kv.w = fmaf(s[j].w, kk, kv.w);
    }
    // Combine the 4 row-groups within the warp (lane xor 8/16 keeps c4).
#pragma unroll
    for (int m = 8; m <= 16; m <<= 1) {
        kv.x += __shfl_xor_sync(0xffffffffu, kv.x, m);
        kv.y += __shfl_xor_sync(0xffffffffu, kv.y, m);
        kv.z += __shfl_xor_sync(0xffffffffu, kv.z, m);
        kv.w += __shfl_xor_sync(0xffffffffu, kv.w, m);
    }
    if ((tid & 31) < 8)
        red_kv[warp][c4] = kv;
    __syncthreads();

    // Reduce the 4 warp partials (redundantly in every thread)
    float4 kvt = make_float4(0.f, 0.f, 0.f, 0.f);
#pragma unroll
    for (int w = 0; w < 4; ++w) {
        const float4 p = red_kv[w][c4];
        kvt.x += p.x; kvt.y += p.y; kvt.z += p.z; kvt.w += p.w;
    }
    // kv_mem = decay * (state . k); delta = (v - kv_mem) * beta
    float4 delta;
    delta.x = (vt.x - decay * kvt.x) * bet;
    delta.y = (vt.y - decay * kvt.y) * bet;
    delta.z = (vt.z - decay * kvt.z) * bet;
    delta.w = (vt.w - decay * kvt.w) * bet;

    // ---- Pass 2: sn = decay*s + k*delta, evict-first store, partial q-dot ----
    float4 acc = make_float4(0.f, 0.f, 0.f, 0.f);
#pragma unroll
    for (int j = 0; j < 8; ++j) {
        const int row = rg * 8 + j;
        const float kk = ks[row];
        float4 sn;
        sn.x = fmaf(decay, s[j].x, kk * delta.x);
        sn.y = fmaf(decay, s[j].y, kk * delta.y);
        sn.z = fmaf(decay, s[j].z, kk * delta.z);
        sn.w = fmaf(decay, s[j].w, kk * delta.w);
        __stcs(&sto4[row * 32 + colbase], sn);
        const float qq = qs[row];
        acc.x = fmaf(sn.x, qq, acc.x);
        acc.y = fmaf(sn.y, qq, acc.y);
        acc.z = fmaf(sn.z, qq, acc.z);
        acc.w = fmaf(sn.w, qq, acc.w);
    }
#pragma unroll
    for (int m = 8; m <= 16; m <<= 1) {
        acc.x += __shfl_xor_sync(0xffffffffu, acc.x, m);
        acc.y += __shfl_xor_sync(0xffffffffu, acc.y, m);
        acc.z += __shfl_xor_sync(0xffffffffu, acc.z, m);
        acc.w += __shfl_xor_sync(0xffffffffu, acc.w, m);
    }
    if ((tid & 31) < 8)
        red_out[warp][c4] = acc;
    __syncthreads();

    // tids 0..7 finish the q-dot and write this slice's output columns
    if (tid < 8) {
        float4 o = make_float4(0.f, 0.f, 0.f, 0.f);
#pragma unroll
        for (int w = 0; w < 4; ++w) {
            const float4 p = red_out[w][c4];
            o.x += p.x; o.y += p.y; o.z += p.z; o.w += p.w;
        }
        ((float4*)(out + (size_t)bh * DV))[cb * 8 + c4] = o;
    }
}

extern "C" void kernel_launch(void* const* d_in, const int* in_sizes, int n_in,
                              void* d_out, int out_size)
{
    const float* q     = (const float*)d_in[0];  // (B,H,1,Dk)
    const float* k     = (const float*)d_in[1];  // (B,H,1,Dk)
    const float* v     = (const float*)d_in[2];  // (B,H,1,Dv)
    const float* g     = (const float*)d_in[3];  // (B,H,1)
    const float* beta  = (const float*)d_in[4];  // (B,H,1)
    const float* state = (const float*)d_in[5];  // (B,H,Dk,Dv)

    float* out       = (float*)d_out;            // first B*H*Dv floats
    float* state_out = out + (size_t)BH * DV;    // then B*H*Dk*Dv floats

    delta_cell_kernel<<<BH * 4, 128>>>(q, k, v, g, beta, state,
                                       out, state_out);
}